// round 4
// baseline (speedup 1.0000x reference)
#include <cuda_runtime.h>
#include <cstdint>

#define Nn 50000
#define Ee 800000
#define Gg 512

// ---------------- scratch (static __device__ allocations) --------------------
__device__ __align__(16) float g_P[(size_t)Nn * 256];    // [N][256]: 0..127 src_p, 128..255 dst_p
__device__ __align__(16) float g_logits[(size_t)Ee * 8]; // per CSR slot, 8 heads
__device__ __align__(16) int   g_deg[Nn];
__device__ __align__(16) int   g_off[Nn + 1];
__device__ __align__(16) int   g_cur[Nn];
__device__ __align__(16) int   g_srcidx[Ee];
__device__ unsigned g_maxenc;
__device__ int      g_gstart[Gg + 1];

// monotonic float<->uint encoding for atomic max
__device__ __forceinline__ unsigned encf(float f) {
    unsigned u = __float_as_uint(f);
    return (u & 0x80000000u) ? ~u : (u | 0x80000000u);
}
__device__ __forceinline__ float decf(unsigned e) {
    unsigned u = (e & 0x80000000u) ? (e & 0x7fffffffu) : ~e;
    return __uint_as_float(u);
}

// ---------------- K0: reset per-launch state ---------------------------------
__global__ void k_init() {
    int i = blockIdx.x * blockDim.x + threadIdx.x;
    if (i < Nn) g_deg[i] = 0;
    if (i == 0) g_maxenc = 0u;
}

// ---------------- K1: P = x @ W^T, 64x64 tile GEMM ---------------------------
// grid: (ceil(N/64), 4); blockIdx.y: bit1 = matrix (src/dst), bit0 = col half
// 256 threads, each computes a 4x4 register tile; k staged in chunks of 16.
__global__ void k_proj(const float* __restrict__ x,
                       const float* __restrict__ Wsrc,
                       const float* __restrict__ Wdst) {
    __shared__ float xs[16 * 64];   // [k][row]
    __shared__ float ws[16 * 64];   // [k][col]
    int m  = blockIdx.y >> 1;
    int ch = blockIdx.y & 1;
    const float* W = m ? Wdst : Wsrc;
    int t  = threadIdx.x;
    int tr = t >> 4, tc = t & 15;
    int rb = blockIdx.x * 64;
    float acc[4][4];
#pragma unroll
    for (int i = 0; i < 4; i++)
#pragma unroll
        for (int j = 0; j < 4; j++) acc[i][j] = 0.f;

    for (int kc = 0; kc < 128; kc += 16) {
        __syncthreads();
#pragma unroll
        for (int u = 0; u < 4; u++) {
            int idx = t + u * 256;       // 1024 elems
            int r = idx & 63, kk = idx >> 6;
            int row = rb + r;
            xs[kk * 64 + r] = (row < Nn) ? x[(size_t)row * 128 + kc + kk] : 0.f;
            ws[kk * 64 + r] = W[(size_t)(ch * 64 + r) * 128 + kc + kk];
        }
        __syncthreads();
#pragma unroll
        for (int kk = 0; kk < 16; kk++) {
            float4 xv = *(const float4*)&xs[kk * 64 + tr * 4];
            float4 wv = *(const float4*)&ws[kk * 64 + tc * 4];
            float xa[4] = {xv.x, xv.y, xv.z, xv.w};
            float wa[4] = {wv.x, wv.y, wv.z, wv.w};
#pragma unroll
            for (int i = 0; i < 4; i++)
#pragma unroll
                for (int j = 0; j < 4; j++) acc[i][j] += xa[i] * wa[j];
        }
    }
#pragma unroll
    for (int i = 0; i < 4; i++) {
        int row = rb + tr * 4 + i;
        if (row < Nn) {
            float4 v = make_float4(acc[i][0], acc[i][1], acc[i][2], acc[i][3]);
            *(float4*)&g_P[(size_t)row * 256 + m * 128 + ch * 64 + tc * 4] = v;
        }
    }
}

// ---------------- K2: degree histogram by dst --------------------------------
__global__ void k_deg(const int* __restrict__ ei) {
    int e = blockIdx.x * blockDim.x + threadIdx.x;
    if (e < Ee) atomicAdd(&g_deg[ei[Ee + e]], 1);
}

// ---------------- K3: exclusive scan (single block) --------------------------
__global__ void k_scan() {
    __shared__ int s[1024];
    int t = threadIdx.x;
    int carry = 0;
    for (int base = 0; base < Nn; base += 4096) {
        int i0 = base + t * 4;
        int v0 = (i0     < Nn) ? g_deg[i0]     : 0;
        int v1 = (i0 + 1 < Nn) ? g_deg[i0 + 1] : 0;
        int v2 = (i0 + 2 < Nn) ? g_deg[i0 + 2] : 0;
        int v3 = (i0 + 3 < Nn) ? g_deg[i0 + 3] : 0;
        int ts = v0 + v1 + v2 + v3;
        s[t] = ts;
        __syncthreads();
        for (int off = 1; off < 1024; off <<= 1) {
            int a = 0;
            if (t >= off) a = s[t - off];
            __syncthreads();
            if (t >= off) s[t] += a;
            __syncthreads();
        }
        int incl = s[t], total = s[1023];
        int b0 = carry + incl - ts;
        if (i0     < Nn) { g_off[i0]     = b0;                 g_cur[i0]     = b0; }
        if (i0 + 1 < Nn) { g_off[i0 + 1] = b0 + v0;            g_cur[i0 + 1] = b0 + v0; }
        if (i0 + 2 < Nn) { g_off[i0 + 2] = b0 + v0 + v1;       g_cur[i0 + 2] = b0 + v0 + v1; }
        if (i0 + 3 < Nn) { g_off[i0 + 3] = b0 + v0 + v1 + v2;  g_cur[i0 + 3] = b0 + v0 + v1 + v2; }
        carry += total;
        __syncthreads();
    }
    if (t == 0) g_off[Nn] = carry;
}

// ---------------- K4: scatter edges into CSR slots ---------------------------
__global__ void k_scatter(const int* __restrict__ ei) {
    int e = blockIdx.x * blockDim.x + threadIdx.x;
    if (e < Ee) {
        int d = ei[Ee + e];
        int pos = atomicAdd(&g_cur[d], 1);
        g_srcidx[pos] = ei[e];
    }
}

// ---------------- K5: per-node attention logits + global max -----------------
// one warp per dst node; lane l owns channels [4l,4l+4)
__global__ void k_logits(const float* __restrict__ attn) {
    int wid = (blockIdx.x * blockDim.x + threadIdx.x) >> 5;
    int l = threadIdx.x & 31;
    if (wid >= Nn) return;
    int n = wid;
    float4 dp, at;
    dp.x = g_P[(size_t)n * 256 + 128 + 4 * l];
    dp.y = g_P[(size_t)n * 256 + 128 + 4 * l + 1];
    dp.z = g_P[(size_t)n * 256 + 128 + 4 * l + 2];
    dp.w = g_P[(size_t)n * 256 + 128 + 4 * l + 3];
    at.x = attn[4 * l]; at.y = attn[4 * l + 1];
    at.z = attn[4 * l + 2]; at.w = attn[4 * l + 3];
    int beg = g_off[n], end = g_off[n + 1];
    float m = -3.402823466e38f;
    for (int i = beg; i < end; i++) {
        int s = g_srcidx[i];
        const float4 sp = *(const float4*)&g_P[(size_t)s * 256 + 4 * l];
        float ex = sp.x + dp.x; ex = ex > 0.f ? ex : 0.2f * ex;
        float ey = sp.y + dp.y; ey = ey > 0.f ? ey : 0.2f * ey;
        float ez = sp.z + dp.z; ez = ez > 0.f ? ez : 0.2f * ez;
        float ew = sp.w + dp.w; ew = ew > 0.f ? ew : 0.2f * ew;
        float p = ex * at.x + ey * at.y + ez * at.z + ew * at.w;
        p += __shfl_xor_sync(0xffffffffu, p, 1);
        p += __shfl_xor_sync(0xffffffffu, p, 2);
        if ((l & 3) == 0) g_logits[(size_t)i * 8 + (l >> 2)] = p;
        m = fmaxf(m, p);
    }
    if (beg < end) {
        for (int o = 16; o; o >>= 1) m = fmaxf(m, __shfl_xor_sync(0xffffffffu, m, o));
        if (l == 0) atomicMax(&g_maxenc, encf(m));
    }
}

// ---------------- K6: softmax + aggregation + residual + PReLU ---------------
__global__ void k_aggr(const float* __restrict__ x, const float* __restrict__ bias,
                       const float* __restrict__ prelu, float* out) {
    int wid = (blockIdx.x * blockDim.x + threadIdx.x) >> 5;
    int l = threadIdx.x & 31;
    if (wid >= Nn) return;
    int n = wid;
    float M = decf(g_maxenc);
    int h = l >> 2;
    int beg = g_off[n], end = g_off[n + 1];
    float den = 0.f;
    for (int i = beg; i < end; i++) den += __expf(g_logits[(size_t)i * 8 + h] - M);
    den += 1e-16f;
    float inv = 1.f / den;
    float4 acc = make_float4(0.f, 0.f, 0.f, 0.f);
    for (int i = beg; i < end; i++) {
        int s = g_srcidx[i];
        float a = __expf(g_logits[(size_t)i * 8 + h] - M) * inv;
        const float4 sp = *(const float4*)&g_P[(size_t)s * 256 + 4 * l];
        acc.x += a * sp.x; acc.y += a * sp.y; acc.z += a * sp.z; acc.w += a * sp.w;
    }
    float al = prelu[0];
    float o0 = acc.x + x[(size_t)n * 128 + 4 * l]     + bias[4 * l];
    float o1 = acc.y + x[(size_t)n * 128 + 4 * l + 1] + bias[4 * l + 1];
    float o2 = acc.z + x[(size_t)n * 128 + 4 * l + 2] + bias[4 * l + 2];
    float o3 = acc.w + x[(size_t)n * 128 + 4 * l + 3] + bias[4 * l + 3];
    o0 = o0 > 0.f ? o0 : al * o0;
    o1 = o1 > 0.f ? o1 : al * o1;
    o2 = o2 > 0.f ? o2 : al * o2;
    o3 = o3 > 0.f ? o3 : al * o3;
    out[(size_t)n * 128 + 4 * l]     = o0;
    out[(size_t)n * 128 + 4 * l + 1] = o1;
    out[(size_t)n * 128 + 4 * l + 2] = o2;
    out[(size_t)n * 128 + 4 * l + 3] = o3;
}

// ---------------- Kb: per-graph node ranges (batch is sorted) ----------------
__global__ void k_bounds(const int* __restrict__ batch) {
    int g = threadIdx.x;  // 512 threads
    int lo = 0, hi = Nn;
    while (lo < hi) {
        int mid = (lo + hi) >> 1;
        if (batch[mid] < g) lo = mid + 1; else hi = mid;
    }
    g_gstart[g] = lo;
    if (g == 0) g_gstart[Gg] = Nn;
}

// ---------------- K7: readout — one block per graph, two column halves -------
__global__ void k_readout(const float* nodeout, const float* __restrict__ ww,
                          const float* __restrict__ bw, const float* __restrict__ Wsc,
                          const float* __restrict__ bsc, float* dout) {
    __shared__ float Wsm[64 * 132];
    __shared__ float xs[8 * 128];
    __shared__ float wws[128];
    __shared__ float wghts[8];
    __shared__ float comb[256];
    int t = threadIdx.x;
    int g = blockIdx.x;
    if (t < 128) wws[t] = ww[t];
    int beg = g_gstart[g], end = g_gstart[g + 1];
    int j = t & 63, q = t >> 6;       // col in half, row group
    float bw0 = bw[0];

    for (int chh = 0; chh < 2; chh++) {
        __syncthreads();
        for (int idx = t; idx < 64 * 128; idx += 256) {
            int r = idx >> 7, k = idx & 127;
            Wsm[r * 132 + k] = Wsc[(size_t)(chh * 64 + r) * 128 + k];
        }
        int jj = chh * 64 + j;
        float bj = bsc[jj];
        float sum_j = 0.f, mx_j = -3.402823466e38f;
        for (int n0 = beg; n0 < end; n0 += 8) {
            int cnt = min(8, end - n0);
            __syncthreads();
            for (int idx = t; idx < 8 * 128; idx += 256) {
                int r = idx >> 7, k = idx & 127;
                xs[idx] = (r < cnt) ? nodeout[(size_t)(n0 + r) * 128 + k] : 0.f;
            }
            __syncthreads();
            {   // gating weight per row: warp w handles row w
                int w = t >> 5, ln = t & 31;
                float v = xs[w * 128 + ln] * wws[ln] + xs[w * 128 + ln + 32] * wws[ln + 32] +
                          xs[w * 128 + ln + 64] * wws[ln + 64] + xs[w * 128 + ln + 96] * wws[ln + 96];
                for (int o = 16; o; o >>= 1) v += __shfl_xor_sync(0xffffffffu, v, o);
                if (ln == 0) wghts[w] = (w < cnt) ? 1.f / (1.f + __expf(-(v + bw0))) : 0.f;
            }
            __syncthreads();
#pragma unroll
            for (int i = 0; i < 2; i++) {
                int r = q * 2 + i;
                float sc = 0.f;
                for (int k = 0; k < 128; k += 4) {
                    sc += Wsm[j * 132 + k]     * xs[r * 128 + k] +
                          Wsm[j * 132 + k + 1] * xs[r * 128 + k + 1] +
                          Wsm[j * 132 + k + 2] * xs[r * 128 + k + 2] +
                          Wsm[j * 132 + k + 3] * xs[r * 128 + k + 3];
                }
                sum_j += wghts[r] * (sc + bj);
                if (r < cnt) mx_j = fmaxf(mx_j, xs[r * 128 + jj]);
            }
        }
        __syncthreads();
        comb[t] = sum_j;
        __syncthreads();
        if (t < 64)
            dout[(size_t)Nn * 128 + g * 256 + jj] =
                comb[t] + comb[64 + t] + comb[128 + t] + comb[192 + t];
        __syncthreads();
        comb[t] = mx_j;
        __syncthreads();
        if (t < 64)
            dout[(size_t)Nn * 128 + g * 256 + 128 + jj] =
                fmaxf(fmaxf(comb[t], comb[64 + t]), fmaxf(comb[128 + t], comb[192 + t]));
    }
}

// ---------------- launch ------------------------------------------------------
extern "C" void kernel_launch(void* const* d_in, const int* in_sizes, int n_in,
                              void* d_out, int out_size) {
    const float* x     = (const float*)d_in[0];
    const int*   ei    = (const int*)d_in[1];
    const int*   batch = (const int*)d_in[2];
    const float* Wsrc  = (const float*)d_in[3];
    const float* Wdst  = (const float*)d_in[4];
    const float* attn  = (const float*)d_in[5];
    const float* bias  = (const float*)d_in[6];
    const float* prelu = (const float*)d_in[7];
    const float* ww    = (const float*)d_in[8];
    const float* bw    = (const float*)d_in[9];
    const float* Wsc   = (const float*)d_in[10];
    const float* bsc   = (const float*)d_in[11];
    float*       out   = (float*)d_out;

    k_init<<<(Nn + 255) / 256, 256>>>();
    dim3 g1((Nn + 63) / 64, 4);
    k_proj<<<g1, 256>>>(x, Wsrc, Wdst);
    k_deg<<<(Ee + 255) / 256, 256>>>(ei);
    k_scan<<<1, 1024>>>();
    k_scatter<<<(Ee + 255) / 256, 256>>>(ei);
    k_logits<<<Nn / 8, 256>>>(attn);
    k_aggr<<<Nn / 8, 256>>>(x, bias, prelu, out);
    k_bounds<<<1, 512>>>(batch);
    k_readout<<<Gg, 256>>>(out, ww, bw, Wsc, bsc, out);
}

// round 5
// speedup vs baseline: 1.0691x; 1.0691x over previous
#include <cuda_runtime.h>
#include <cstdint>

#define Nn 50000
#define Ee 800000
#define Gg 512
#define NBLK 196   // ceil(Nn/256)

// ---------------- scratch ----------------------------------------------------
__device__ __align__(16) float g_P[(size_t)Nn * 256];    // [N][256]: 0..127 src_p, 128..255 dst_p
__device__ __align__(16) float g_logits[(size_t)Ee * 8];
__device__ __align__(16) int   g_deg[Nn];
__device__ __align__(16) int   g_off[Nn + 1];
__device__ __align__(16) int   g_cur[Nn];
__device__ __align__(16) int   g_srcidx[Ee];
__device__ __align__(16) int   g_part[256];
__device__ unsigned g_maxenc;
__device__ int      g_gstart[Gg + 1];

// ---------------- f32x2 packed helpers ---------------------------------------
typedef unsigned long long u64;
__device__ __forceinline__ u64 p2(float lo, float hi) {
    u64 r;
    asm("mov.b64 %0, {%1, %2};" : "=l"(r) : "r"(__float_as_uint(lo)), "r"(__float_as_uint(hi)));
    return r;
}
__device__ __forceinline__ void fma2(u64& d, u64 a, u64 b) {
    asm("fma.rn.f32x2 %0, %1, %2, %3;" : "=l"(d) : "l"(a), "l"(b), "l"(d));
}
__device__ __forceinline__ float2 up2(u64 v) {
    unsigned lo, hi;
    asm("mov.b64 {%0, %1}, %2;" : "=r"(lo), "=r"(hi) : "l"(v));
    return make_float2(__uint_as_float(lo), __uint_as_float(hi));
}

__device__ __forceinline__ unsigned encf(float f) {
    unsigned u = __float_as_uint(f);
    return (u & 0x80000000u) ? ~u : (u | 0x80000000u);
}
__device__ __forceinline__ float decf(unsigned e) {
    unsigned u = (e & 0x80000000u) ? (e & 0x7fffffffu) : ~e;
    return __uint_as_float(u);
}

// ---------------- K0: init deg + maxenc + graph bounds -----------------------
__global__ void k_pre(const int* __restrict__ batch) {
    int i = blockIdx.x * 256 + threadIdx.x;
    if (i < Nn) g_deg[i] = 0;
    if (i == 0) g_maxenc = 0u;
    if (i < Gg) {   // binary search for graph starts (batch sorted)
        int lo = 0, hi = Nn;
        while (lo < hi) {
            int mid = (lo + hi) >> 1;
            if (batch[mid] < i) lo = mid + 1; else hi = mid;
        }
        g_gstart[i] = lo;
        if (i == 0) g_gstart[Gg] = Nn;
    }
}

// ---------------- K1: P = x @ W^T, 64x64 tile, packed FFMA2 ------------------
__global__ void k_proj(const float* __restrict__ x,
                       const float* __restrict__ Wsrc,
                       const float* __restrict__ Wdst) {
    __shared__ __align__(16) float xs[16 * 64];   // [k][row]
    __shared__ __align__(16) float ws[16 * 64];   // [k][col]
    int m  = blockIdx.y >> 1;
    int ch = blockIdx.y & 1;
    const float* W = m ? Wdst : Wsrc;
    int t  = threadIdx.x;
    int tr = t >> 4, tc = t & 15;
    int rb = blockIdx.x * 64;
    u64 acc[4][2];
#pragma unroll
    for (int i = 0; i < 4; i++) { acc[i][0] = 0ull; acc[i][1] = 0ull; }

    for (int kc = 0; kc < 128; kc += 16) {
        __syncthreads();
#pragma unroll
        for (int u = 0; u < 4; u++) {
            int idx = t + u * 256;
            int r = idx & 63, kk = idx >> 6;
            int row = rb + r;
            xs[kk * 64 + r] = (row < Nn) ? x[(size_t)row * 128 + kc + kk] : 0.f;
            ws[kk * 64 + r] = W[(size_t)(ch * 64 + r) * 128 + kc + kk];
        }
        __syncthreads();
#pragma unroll
        for (int kk = 0; kk < 16; kk++) {
            float4 xv = *(const float4*)&xs[kk * 64 + tr * 4];
            ulonglong2 wv = *(const ulonglong2*)&ws[kk * 64 + tc * 4];
            u64 xd0 = p2(xv.x, xv.x), xd1 = p2(xv.y, xv.y);
            u64 xd2 = p2(xv.z, xv.z), xd3 = p2(xv.w, xv.w);
            fma2(acc[0][0], xd0, wv.x); fma2(acc[0][1], xd0, wv.y);
            fma2(acc[1][0], xd1, wv.x); fma2(acc[1][1], xd1, wv.y);
            fma2(acc[2][0], xd2, wv.x); fma2(acc[2][1], xd2, wv.y);
            fma2(acc[3][0], xd3, wv.x); fma2(acc[3][1], xd3, wv.y);
        }
    }
#pragma unroll
    for (int i = 0; i < 4; i++) {
        int row = rb + tr * 4 + i;
        if (row < Nn) {
            ulonglong2 v; v.x = acc[i][0]; v.y = acc[i][1];
            *(ulonglong2*)&g_P[(size_t)row * 256 + m * 128 + ch * 64 + tc * 4] = v;
        }
    }
}

// ---------------- K2: degree histogram ---------------------------------------
__global__ void k_deg(const int* __restrict__ ei) {
    int e = blockIdx.x * blockDim.x + threadIdx.x;
    if (e < Ee) atomicAdd(&g_deg[ei[Ee + e]], 1);
}

// ---------------- K3a/b/c: multi-block exclusive scan ------------------------
__global__ void k_scanA() {
    int b = blockIdx.x, t = threadIdx.x;
    int i = b * 256 + t;
    int v = (i < Nn) ? g_deg[i] : 0;
#pragma unroll
    for (int o = 16; o; o >>= 1) v += __shfl_xor_sync(0xffffffffu, v, o);
    __shared__ int sm[8];
    if ((t & 31) == 0) sm[t >> 5] = v;
    __syncthreads();
    if (t == 0) {
        int s = 0;
#pragma unroll
        for (int w = 0; w < 8; w++) s += sm[w];
        g_part[b] = s;
    }
}
__global__ void k_scanB() {
    int t = threadIdx.x;          // 256
    int v = (t < NBLK) ? g_part[t] : 0;
    int orig = v;
    int lane = t & 31, w = t >> 5;
#pragma unroll
    for (int o = 1; o < 32; o <<= 1) {
        int u = __shfl_up_sync(0xffffffffu, v, o);
        if (lane >= o) v += u;
    }
    __shared__ int wsum[8];
    if (lane == 31) wsum[w] = v;
    __syncthreads();
    if (w == 0) {
        int z = (lane < 8) ? wsum[lane] : 0;
#pragma unroll
        for (int o = 1; o < 8; o <<= 1) {
            int u = __shfl_up_sync(0xffffffffu, z, o);
            if (lane >= o) z += u;
        }
        if (lane < 8) wsum[lane] = z;
    }
    __syncthreads();
    int incl = v + (w ? wsum[w - 1] : 0);
    g_part[t] = incl - orig;          // exclusive prefix of block partials
    if (t == 255) g_off[Nn] = incl;   // grand total
}
__global__ void k_scanC() {
    int b = blockIdx.x, t = threadIdx.x;
    int i = b * 256 + t;
    int v = (i < Nn) ? g_deg[i] : 0;
    int orig = v;
    int lane = t & 31, w = t >> 5;
#pragma unroll
    for (int o = 1; o < 32; o <<= 1) {
        int u = __shfl_up_sync(0xffffffffu, v, o);
        if (lane >= o) v += u;
    }
    __shared__ int wsum[8];
    if (lane == 31) wsum[w] = v;
    __syncthreads();
    if (w == 0) {
        int z = (lane < 8) ? wsum[lane] : 0;
#pragma unroll
        for (int o = 1; o < 8; o <<= 1) {
            int u = __shfl_up_sync(0xffffffffu, z, o);
            if (lane >= o) z += u;
        }
        if (lane < 8) wsum[lane] = z;
    }
    __syncthreads();
    int excl = v - orig + (w ? wsum[w - 1] : 0) + g_part[b];
    if (i < Nn) { g_off[i] = excl; g_cur[i] = excl; }
}

// ---------------- K4: scatter edges into CSR slots ---------------------------
__global__ void k_scatter(const int* __restrict__ ei) {
    int e = blockIdx.x * blockDim.x + threadIdx.x;
    if (e < Ee) {
        int d = ei[Ee + e];
        int pos = atomicAdd(&g_cur[d], 1);
        g_srcidx[pos] = ei[e];
    }
}

// ---------------- K5: logits + global max (warp/node, 2-edge unroll) ---------
__global__ void k_logits(const float* __restrict__ attn) {
    int wid = (blockIdx.x * blockDim.x + threadIdx.x) >> 5;
    int l = threadIdx.x & 31;
    if (wid >= Nn) return;
    int n = wid;
    const float4 dp = *(const float4*)&g_P[(size_t)n * 256 + 128 + 4 * l];
    float a0 = attn[4 * l], a1 = attn[4 * l + 1], a2 = attn[4 * l + 2], a3 = attn[4 * l + 3];
    float a0q = 0.2f * a0, a1q = 0.2f * a1, a2q = 0.2f * a2, a3q = 0.2f * a3;
    int beg = g_off[n], end = g_off[n + 1];
    float m = -3.402823466e38f;
    int i = beg;
    for (; i + 1 < end; i += 2) {
        int s0 = g_srcidx[i], s1 = g_srcidx[i + 1];
        const float4 q0 = *(const float4*)&g_P[(size_t)s0 * 256 + 4 * l];
        const float4 q1 = *(const float4*)&g_P[(size_t)s1 * 256 + 4 * l];
        float ex, ey, ez, ew, p0, p1;
        ex = q0.x + dp.x; ey = q0.y + dp.y; ez = q0.z + dp.z; ew = q0.w + dp.w;
        p0 = a0 * fmaxf(ex, 0.f) + a0q * fminf(ex, 0.f)
           + a1 * fmaxf(ey, 0.f) + a1q * fminf(ey, 0.f)
           + a2 * fmaxf(ez, 0.f) + a2q * fminf(ez, 0.f)
           + a3 * fmaxf(ew, 0.f) + a3q * fminf(ew, 0.f);
        ex = q1.x + dp.x; ey = q1.y + dp.y; ez = q1.z + dp.z; ew = q1.w + dp.w;
        p1 = a0 * fmaxf(ex, 0.f) + a0q * fminf(ex, 0.f)
           + a1 * fmaxf(ey, 0.f) + a1q * fminf(ey, 0.f)
           + a2 * fmaxf(ez, 0.f) + a2q * fminf(ez, 0.f)
           + a3 * fmaxf(ew, 0.f) + a3q * fminf(ew, 0.f);
        p0 += __shfl_xor_sync(0xffffffffu, p0, 1);
        p1 += __shfl_xor_sync(0xffffffffu, p1, 1);
        p0 += __shfl_xor_sync(0xffffffffu, p0, 2);
        p1 += __shfl_xor_sync(0xffffffffu, p1, 2);
        if ((l & 3) == 0) {
            g_logits[(size_t)i * 8 + (l >> 2)] = p0;
            g_logits[(size_t)(i + 1) * 8 + (l >> 2)] = p1;
        }
        m = fmaxf(m, fmaxf(p0, p1));
    }
    if (i < end) {
        int s0 = g_srcidx[i];
        const float4 q0 = *(const float4*)&g_P[(size_t)s0 * 256 + 4 * l];
        float ex = q0.x + dp.x, ey = q0.y + dp.y, ez = q0.z + dp.z, ew = q0.w + dp.w;
        float p0 = a0 * fmaxf(ex, 0.f) + a0q * fminf(ex, 0.f)
                 + a1 * fmaxf(ey, 0.f) + a1q * fminf(ey, 0.f)
                 + a2 * fmaxf(ez, 0.f) + a2q * fminf(ez, 0.f)
                 + a3 * fmaxf(ew, 0.f) + a3q * fminf(ew, 0.f);
        p0 += __shfl_xor_sync(0xffffffffu, p0, 1);
        p0 += __shfl_xor_sync(0xffffffffu, p0, 2);
        if ((l & 3) == 0) g_logits[(size_t)i * 8 + (l >> 2)] = p0;
        m = fmaxf(m, p0);
    }
    if (beg < end) {
        for (int o = 16; o; o >>= 1) m = fmaxf(m, __shfl_xor_sync(0xffffffffu, m, o));
        if (l == 0) atomicMax(&g_maxenc, encf(m));
    }
}

// ---------------- K6: softmax + aggregation + residual + PReLU ---------------
__global__ void k_aggr(const float* __restrict__ x, const float* __restrict__ bias,
                       const float* __restrict__ prelu, float* out) {
    int wid = (blockIdx.x * blockDim.x + threadIdx.x) >> 5;
    int l = threadIdx.x & 31;
    if (wid >= Nn) return;
    int n = wid;
    float M = decf(g_maxenc);
    int h = l >> 2;
    int beg = g_off[n], end = g_off[n + 1];
    float den = 0.f;
    {
        int i = beg;
        for (; i + 3 < end; i += 4) {
            float t0 = g_logits[(size_t)i * 8 + h];
            float t1 = g_logits[(size_t)(i + 1) * 8 + h];
            float t2 = g_logits[(size_t)(i + 2) * 8 + h];
            float t3 = g_logits[(size_t)(i + 3) * 8 + h];
            den += __expf(t0 - M) + __expf(t1 - M) + __expf(t2 - M) + __expf(t3 - M);
        }
        for (; i < end; i++) den += __expf(g_logits[(size_t)i * 8 + h] - M);
    }
    den += 1e-16f;
    float inv = __fdividef(1.f, den);
    float4 acc = make_float4(0.f, 0.f, 0.f, 0.f);
    int i = beg;
    for (; i + 1 < end; i += 2) {
        int s0 = g_srcidx[i], s1 = g_srcidx[i + 1];
        float w0 = __expf(g_logits[(size_t)i * 8 + h] - M) * inv;
        float w1 = __expf(g_logits[(size_t)(i + 1) * 8 + h] - M) * inv;
        const float4 q0 = *(const float4*)&g_P[(size_t)s0 * 256 + 4 * l];
        const float4 q1 = *(const float4*)&g_P[(size_t)s1 * 256 + 4 * l];
        acc.x += w0 * q0.x + w1 * q1.x;
        acc.y += w0 * q0.y + w1 * q1.y;
        acc.z += w0 * q0.z + w1 * q1.z;
        acc.w += w0 * q0.w + w1 * q1.w;
    }
    if (i < end) {
        int s0 = g_srcidx[i];
        float w0 = __expf(g_logits[(size_t)i * 8 + h] - M) * inv;
        const float4 q0 = *(const float4*)&g_P[(size_t)s0 * 256 + 4 * l];
        acc.x += w0 * q0.x; acc.y += w0 * q0.y; acc.z += w0 * q0.z; acc.w += w0 * q0.w;
    }
    const float4 xv = *(const float4*)&x[(size_t)n * 128 + 4 * l];
    const float4 bv = *(const float4*)&bias[4 * l];
    float al = prelu[0];
    float o0 = acc.x + xv.x + bv.x; o0 = o0 > 0.f ? o0 : al * o0;
    float o1 = acc.y + xv.y + bv.y; o1 = o1 > 0.f ? o1 : al * o1;
    float o2 = acc.z + xv.z + bv.z; o2 = o2 > 0.f ? o2 : al * o2;
    float o3 = acc.w + xv.w + bv.w; o3 = o3 > 0.f ? o3 : al * o3;
    out[(size_t)n * 128 + 4 * l]     = o0;
    out[(size_t)n * 128 + 4 * l + 1] = o1;
    out[(size_t)n * 128 + 4 * l + 2] = o2;
    out[(size_t)n * 128 + 4 * l + 3] = o3;
}

// ---------------- K7: readout — one block per graph, packed FFMA2 ------------
__global__ void k_readout(const float* nodeout, const float* __restrict__ ww,
                          const float* __restrict__ bw, const float* __restrict__ Wsc,
                          const float* __restrict__ bsc, float* dout) {
    __shared__ __align__(16) float Wsm[64 * 132];
    __shared__ __align__(16) float xs[8 * 128];
    __shared__ float wws[128];
    __shared__ float wghts[8];
    __shared__ float comb[256];
    int t = threadIdx.x;
    int g = blockIdx.x;
    if (t < 128) wws[t] = ww[t];
    int beg = g_gstart[g], end = g_gstart[g + 1];
    int j = t & 63, q = t >> 6;
    float bw0 = bw[0];

    for (int chh = 0; chh < 2; chh++) {
        __syncthreads();
        for (int idx = t; idx < 64 * 128; idx += 256) {
            int r = idx >> 7, k = idx & 127;
            Wsm[r * 132 + k] = Wsc[(size_t)(chh * 64 + r) * 128 + k];
        }
        int jj = chh * 64 + j;
        float bj = bsc[jj];
        float sum_j = 0.f, mx_j = -3.402823466e38f;
        for (int n0 = beg; n0 < end; n0 += 8) {
            int cnt = min(8, end - n0);
            __syncthreads();
            for (int idx = t; idx < 8 * 128; idx += 256) {
                int r = idx >> 7, k = idx & 127;
                xs[idx] = (r < cnt) ? nodeout[(size_t)(n0 + r) * 128 + k] : 0.f;
            }
            __syncthreads();
            {
                int w = t >> 5, ln = t & 31;
                float v = xs[w * 128 + ln] * wws[ln] + xs[w * 128 + ln + 32] * wws[ln + 32] +
                          xs[w * 128 + ln + 64] * wws[ln + 64] + xs[w * 128 + ln + 96] * wws[ln + 96];
                for (int o = 16; o; o >>= 1) v += __shfl_xor_sync(0xffffffffu, v, o);
                if (ln == 0) wghts[w] = (w < cnt) ? 1.f / (1.f + __expf(-(v + bw0))) : 0.f;
            }
            __syncthreads();
#pragma unroll
            for (int i2 = 0; i2 < 2; i2++) {
                int r = q * 2 + i2;
                u64 s2 = 0ull;
                for (int k = 0; k < 128; k += 8) {
                    ulonglong2 wv = *(const ulonglong2*)&Wsm[j * 132 + k];
                    ulonglong2 xv = *(const ulonglong2*)&xs[r * 128 + k];
                    ulonglong2 wv2 = *(const ulonglong2*)&Wsm[j * 132 + k + 4];
                    ulonglong2 xv2 = *(const ulonglong2*)&xs[r * 128 + k + 4];
                    fma2(s2, wv.x, xv.x); fma2(s2, wv.y, xv.y);
                    fma2(s2, wv2.x, xv2.x); fma2(s2, wv2.y, xv2.y);
                }
                float2 sp = up2(s2);
                float sc = sp.x + sp.y;
                sum_j += wghts[r] * (sc + bj);
                if (r < cnt) mx_j = fmaxf(mx_j, xs[r * 128 + jj]);
            }
        }
        __syncthreads();
        comb[t] = sum_j;
        __syncthreads();
        if (t < 64)
            dout[(size_t)Nn * 128 + g * 256 + jj] =
                comb[t] + comb[64 + t] + comb[128 + t] + comb[192 + t];
        __syncthreads();
        comb[t] = mx_j;
        __syncthreads();
        if (t < 64)
            dout[(size_t)Nn * 128 + g * 256 + 128 + jj] =
                fmaxf(fmaxf(comb[t], comb[64 + t]), fmaxf(comb[128 + t], comb[192 + t]));
    }
}

// ---------------- launch ------------------------------------------------------
extern "C" void kernel_launch(void* const* d_in, const int* in_sizes, int n_in,
                              void* d_out, int out_size) {
    const float* x     = (const float*)d_in[0];
    const int*   ei    = (const int*)d_in[1];
    const int*   batch = (const int*)d_in[2];
    const float* Wsrc  = (const float*)d_in[3];
    const float* Wdst  = (const float*)d_in[4];
    const float* attn  = (const float*)d_in[5];
    const float* bias  = (const float*)d_in[6];
    const float* prelu = (const float*)d_in[7];
    const float* ww    = (const float*)d_in[8];
    const float* bw    = (const float*)d_in[9];
    const float* Wsc   = (const float*)d_in[10];
    const float* bsc   = (const float*)d_in[11];
    float*       out   = (float*)d_out;

    k_pre<<<NBLK, 256>>>(batch);
    dim3 g1((Nn + 63) / 64, 4);
    k_proj<<<g1, 256>>>(x, Wsrc, Wdst);
    k_deg<<<(Ee + 511) / 512, 512>>>(ei);
    k_scanA<<<NBLK, 256>>>();
    k_scanB<<<1, 256>>>();
    k_scanC<<<NBLK, 256>>>();
    k_scatter<<<(Ee + 511) / 512, 512>>>(ei);
    k_logits<<<Nn / 8, 256>>>(attn);
    k_aggr<<<Nn / 8, 256>>>(x, bias, prelu, out);
    k_readout<<<Gg, 256>>>(out, ww, bw, Wsc, bsc, out);
}